// round 10
// baseline (speedup 1.0000x reference)
#include <cuda_runtime.h>
#include <cuda_bf16.h>
#include <cstdint>

// LinearMultiheadSplit: out[n] = x[n] @ (W[head] + 0.1*D[head*4+split]) + bias[head]
// N=1024, IN=OUT=512, 32 heads x 4 splits -> 128 combos.
//
// v6 (resubmit; R9 was an infra flake): cp.async smem-staged streaming.
//  - 1 block per combo (128 blocks, single wave, 1 block/SM), 256 threads x 2 cols
//  - W/D streamed through a 4-stage x 8-k smem ring via cp.async.cg (96 KB in
//    flight per SM -- latency hiding no longer depends on warp count/registers)
//  - no k-split, no cross-group reduction; full k per thread, acc in 32 regs
//  - packed fma.rn.f32x2: 2 samples per 64-bit lane; PAIRS template 4/8

#define N_SAMPLES 1024
#define IN_F      512
#define OUT_F     512
#define N_HEADS   32
#define N_SPLITS  4
#define N_COMBO   128
#define THREADS   256
#define CHUNK     16
#define KSTAGE    8
#define NSTAGES   4
#define NSTEPS    (IN_F / KSTAGE)          // 64
#define ROWF2     (OUT_F / 2)              // 256 float2 per k-row
#define STAGE_BYTES (KSTAGE * OUT_F * 4)   // 16384

// dynamic smem layout (all offsets 16B-aligned)
#define OFF_CNT   0
#define OFF_LIST  16                                  // short[1024] -> 2048 B
#define OFF_XS    2064                                // float[512*16] = 32768 B
#define OFF_SW    (OFF_XS + IN_F * CHUNK * 4)         // 34832, 4 stages x 16384
#define OFF_SD    (OFF_SW + NSTAGES * STAGE_BYTES)    // 100368
#define SMEM_TOTAL (OFF_SD + NSTAGES * STAGE_BYTES)   // 165904 B

__device__ __forceinline__ unsigned long long dup2(float v) {
    unsigned long long r; unsigned u = __float_as_uint(v);
    asm("mov.b64 %0, {%1, %1};" : "=l"(r) : "r"(u));
    return r;
}
__device__ __forceinline__ unsigned long long fma2(unsigned long long a,
                                                   unsigned long long b,
                                                   unsigned long long c) {
    unsigned long long d;
    asm("fma.rn.f32x2 %0, %1, %2, %3;" : "=l"(d) : "l"(a), "l"(b), "l"(c));
    return d;
}
__device__ __forceinline__ void unpack2(unsigned long long v, float& lo, float& hi) {
    unsigned a, b;
    asm("mov.b64 {%0, %1}, %2;" : "=r"(a), "=r"(b) : "l"(v));
    lo = __uint_as_float(a); hi = __uint_as_float(b);
}
template <int N>
__device__ __forceinline__ void cp_wait() {
    asm volatile("cp.async.wait_group %0;" :: "n"(N) : "memory");
}

// Issue one 8-k stage of W and D into ring buffer (st & 3).
// Stage source is a contiguous 16 KB block (full 512-col rows). Each thread
// copies 4 x 16B per tensor. One commit_group per stage.
__device__ __forceinline__ void issue_stage(unsigned sw_u32, unsigned sd_u32,
                                            const char* wg, const char* dg,
                                            int st, int tid)
{
    const unsigned b   = (unsigned)(st & (NSTAGES - 1)) * STAGE_BYTES;
    const unsigned off = (unsigned)tid * 16u;
    const char* ws = wg + (size_t)st * STAGE_BYTES;
    const char* ds = dg + (size_t)st * STAGE_BYTES;
#pragma unroll
    for (int i = 0; i < 4; ++i) {
        asm volatile("cp.async.cg.shared.global [%0], [%1], 16;"
                     :: "r"(sw_u32 + b + off + (unsigned)(i * 4096)),
                        "l"(ws + off + i * 4096) : "memory");
        asm volatile("cp.async.cg.shared.global [%0], [%1], 16;"
                     :: "r"(sd_u32 + b + off + (unsigned)(i * 4096)),
                        "l"(ds + off + i * 4096) : "memory");
    }
    asm volatile("cp.async.commit_group;" ::: "memory");
}

// Compute one 8-k stage from ring buffer (st & 3).
template <int PAIRS>
__device__ __forceinline__ void compute_stage(const float* __restrict__ swf,
                                              const float* __restrict__ sdf,
                                              unsigned xa, int st, int tid,
                                              unsigned long long* acc)
{
    const int b = st & (NSTAGES - 1);
    const float2* wr = (const float2*)(swf + b * (KSTAGE * OUT_F)) + tid;
    const float2* dr = (const float2*)(sdf + b * (KSTAGE * OUT_F)) + tid;
    const unsigned xk = xa + (unsigned)(st * KSTAGE) * (CHUNK * 4);
#pragma unroll
    for (int j = 0; j < KSTAGE; ++j) {
        float2 w2 = wr[j * ROWF2];     // LDS.64, 256B/warp, conflict-free
        float2 d2 = dr[j * ROWF2];
        float wv0 = fmaf(d2.x, 0.1f, w2.x);
        float wv1 = fmaf(d2.y, 0.1f, w2.y);
        unsigned long long wva = dup2(wv0);
        unsigned long long wvb = dup2(wv1);

        unsigned a = xk + (unsigned)j * (CHUNK * 4);
        unsigned long long xp[PAIRS];
#pragma unroll
        for (int p = 0; p < PAIRS; p += 2) {
            asm volatile("ld.shared.v2.b64 {%0,%1},[%2];"
                         : "=l"(xp[p]), "=l"(xp[p + 1]) : "r"(a + (unsigned)(8 * p)));
        }
#pragma unroll
        for (int p = 0; p < PAIRS; ++p) {
            acc[p]         = fma2(xp[p], wva, acc[p]);
            acc[PAIRS + p] = fma2(xp[p], wvb, acc[PAIRS + p]);
        }
    }
}

// Full 64-stage stream + store. All __syncthreads block-uniform.
template <int PAIRS>
__device__ __forceinline__ void run_stream(
    const float* __restrict__ swf, const float* __restrict__ sdf,
    unsigned sw_u32, unsigned sd_u32, unsigned xa,
    const char* wg, const char* dg,
    const short* __restrict__ s_list, int base, int m,
    float2 bv, float* __restrict__ out, int tid)
{
    unsigned long long acc[2 * PAIRS];
#pragma unroll
    for (int j = 0; j < 2 * PAIRS; ++j) acc[j] = 0ull;

    // main loop: stages 0 .. NSTEPS-NSTAGES-1, keep NSTAGES groups in flight
#pragma unroll 1
    for (int st = 0; st < NSTEPS - NSTAGES; ++st) {
        cp_wait<NSTAGES - 1>();
        __syncthreads();                       // stage st data visible to all
        compute_stage<PAIRS>(swf, sdf, xa, st, tid, acc);
        __syncthreads();                       // all done reading buf (st&3)
        issue_stage(sw_u32, sd_u32, wg, dg, st + NSTAGES, tid);
    }
    // tail: drain with decreasing wait counts
    cp_wait<3>(); __syncthreads();
    compute_stage<PAIRS>(swf, sdf, xa, NSTEPS - 4, tid, acc);
    cp_wait<2>(); __syncthreads();
    compute_stage<PAIRS>(swf, sdf, xa, NSTEPS - 3, tid, acc);
    cp_wait<1>(); __syncthreads();
    compute_stage<PAIRS>(swf, sdf, xa, NSTEPS - 2, tid, acc);
    cp_wait<0>(); __syncthreads();
    compute_stage<PAIRS>(swf, sdf, xa, NSTEPS - 1, tid, acc);

    // store: pair p holds samples (2p, 2p+1); acc[p]=col0, acc[PAIRS+p]=col1
    const int c0 = tid * 2;
#pragma unroll
    for (int p = 0; p < PAIRS; ++p) {
        float l0, h0, l1, h1;
        unpack2(acc[p],         l0, h0);
        unpack2(acc[PAIRS + p], l1, h1);
        int i0 = base + 2 * p;
        if (i0 < m) {
            int n = s_list[i0];
            float2 o = make_float2(l0 + bv.x, l1 + bv.y);
            *(float2*)(out + (size_t)n * OUT_F + c0) = o;
        }
        if (i0 + 1 < m) {
            int n = s_list[i0 + 1];
            float2 o = make_float2(h0 + bv.x, h1 + bv.y);
            *(float2*)(out + (size_t)n * OUT_F + c0) = o;
        }
    }
}

__global__ void __launch_bounds__(THREADS)
lms_kernel(const float* __restrict__ X,
           const int* __restrict__ hix,
           const int* __restrict__ six,
           const float* __restrict__ W,
           const float* __restrict__ D,
           const float* __restrict__ B,
           float* __restrict__ out)
{
    extern __shared__ __align__(16) char smem[];
    int*   s_cnt  = (int*)(smem + OFF_CNT);
    short* s_list = (short*)(smem + OFF_LIST);
    float* xs     = (float*)(smem + OFF_XS);
    const float* swf = (const float*)(smem + OFF_SW);
    const float* sdf = (const float*)(smem + OFF_SD);

    const unsigned smem_u32 = (unsigned)__cvta_generic_to_shared(smem);
    const unsigned sw_u32 = smem_u32 + OFF_SW;
    const unsigned sd_u32 = smem_u32 + OFF_SD;
    const unsigned xa     = smem_u32 + OFF_XS;

    const int tid = threadIdx.x;
    const int g   = blockIdx.x;            // combo
    const int h   = g >> 2;
    const int sp  = g & 3;

    // ---- Phase A: build sample list for this combo ----
    if (tid == 0) *s_cnt = 0;
    __syncthreads();
    for (int n = tid; n < N_SAMPLES; n += THREADS) {
        if (hix[n] == h && six[n] == sp) {
            int p = atomicAdd(s_cnt, 1);
            s_list[p] = (short)n;
        }
    }
    __syncthreads();
    const int m = *s_cnt;
    if (m == 0) return;                    // uniform; nothing issued yet

    const char* wg = (const char*)(W + (size_t)h * (IN_F * OUT_F));
    const char* dg = (const char*)(D + (size_t)g * (IN_F * OUT_F));
    const float2 bv = *(const float2*)(B + h * OUT_F + tid * 2);

    // staging mapping: s = tid&15 (sample slot), q0 = tid>>4 (float4 base)
    const int s  = tid & 15;
    const int q0 = tid >> 4;               // 0..15

    // Almost always a single chunk (P[m>16] ~ 0.4% per combo).
    for (int base = 0; base < m; base += CHUNK) {
        // prologue: start the W/D stream before staging x (overlap)
#pragma unroll
        for (int st = 0; st < NSTAGES; ++st)
            issue_stage(sw_u32, sd_u32, wg, dg, st, tid);

        // ---- stage x chunk transposed into smem (zero-padded) ----
        const int  sg    = base + s;
        const bool valid = sg < m;
        const float4* xrow =
            valid ? (const float4*)(X + (size_t)s_list[sg] * IN_F) : (const float4*)X;
#pragma unroll
        for (int i = 0; i < 8; ++i) {
            int Q = q0 + i * 16;           // 0..127
            float4 v = valid ? __ldg(xrow + Q) : make_float4(0.f, 0.f, 0.f, 0.f);
            int k0 = Q * 4;
            xs[(k0 + 0) * CHUNK + s] = v.x;
            xs[(k0 + 1) * CHUNK + s] = v.y;
            xs[(k0 + 2) * CHUNK + s] = v.z;
            xs[(k0 + 3) * CHUNK + s] = v.w;
        }
        __syncthreads();

        int mc = m - base;
        if (mc > CHUNK) mc = CHUNK;

        if (mc > 8)
            run_stream<8>(swf, sdf, sw_u32, sd_u32, xa, wg, dg,
                          s_list, base, m, bv, out, tid);
        else
            run_stream<4>(swf, sdf, sw_u32, sd_u32, xa, wg, dg,
                          s_list, base, m, bv, out, tid);

        __syncthreads();                   // ring fully drained; xs restage safe
    }
}

extern "C" void kernel_launch(void* const* d_in, const int* in_sizes, int n_in,
                              void* d_out, int out_size)
{
    const float* X   = (const float*)d_in[0];
    const int*   hix = (const int*)d_in[1];
    const int*   six = (const int*)d_in[2];
    const float* W   = (const float*)d_in[3];
    const float* D   = (const float*)d_in[4];
    const float* B   = (const float*)d_in[5];
    float*       out = (float*)d_out;

    cudaFuncSetAttribute(lms_kernel,
                         cudaFuncAttributeMaxDynamicSharedMemorySize, SMEM_TOTAL);
    lms_kernel<<<N_COMBO, THREADS, SMEM_TOTAL>>>(X, hix, six, W, D, B, out);
}

// round 13
// speedup vs baseline: 1.8303x; 1.8303x over previous
#include <cuda_runtime.h>
#include <cuda_bf16.h>
#include <cstdint>

// LinearMultiheadSplit: out[n] = x[n] @ (W[head] + 0.1*D[head*4+split]) + bias[head]
// N=1024, IN=OUT=512, 32 heads x 4 splits -> 128 combos.
//
// v7 (resubmit; R11 was an infra flake) = v5 (best: 57.8us) + prefetch loads
// pinned with asm volatile. ptxas was sinking the __ldg prefetches to
// point-of-use (MLP_eff ~6, 11 B/cyc/SM); volatile ld.global.nc.v2.f32
// preserves program-order issue -> true depth-8 pipeline, 16 LDG.64 in
// flight per thread.
//  - 256 blocks (2 col-tiles x 128 combos), 256 threads = 2 k-groups x 128
//  - thread owns 2 cols; k split in-block, smem reduce; barrier-free k-loop
//  - packed fma.rn.f32x2: 2 samples per 64-bit lane; PAIRS template 4/8

#define N_SAMPLES 1024
#define IN_F      512
#define OUT_F     512
#define N_HEADS   32
#define N_SPLITS  4
#define N_COMBO   (N_HEADS * N_SPLITS)
#define THREADS   256
#define KHALF     256          // k per group (2 groups)
#define COLS_PER_BLOCK 256     // 128 threads * 2 cols
#define CHUNK     16           // samples per tile (8 f32x2 pairs max)
#define PIPE      8            // software pipeline depth
#define ROWF2     (OUT_F / 2)  // float2 per k-row = 256

__device__ __forceinline__ unsigned long long dup2(float v) {
    unsigned long long r; unsigned u = __float_as_uint(v);
    asm("mov.b64 %0, {%1, %1};" : "=l"(r) : "r"(u));
    return r;
}
__device__ __forceinline__ unsigned long long fma2(unsigned long long a,
                                                   unsigned long long b,
                                                   unsigned long long c) {
    unsigned long long d;
    asm("fma.rn.f32x2 %0, %1, %2, %3;" : "=l"(d) : "l"(a), "l"(b), "l"(c));
    return d;
}
__device__ __forceinline__ void unpack2(unsigned long long v, float& lo, float& hi) {
    unsigned a, b;
    asm("mov.b64 {%0, %1}, %2;" : "=r"(a), "=r"(b) : "l"(v));
    lo = __uint_as_float(a); hi = __uint_as_float(b);
}
// Pinned streaming load: volatile => ptxas keeps issue position (real MLP).
__device__ __forceinline__ float2 ldg2v(const float2* p) {
    float2 v;
    asm volatile("ld.global.nc.v2.f32 {%0,%1}, [%2];"
                 : "=f"(v.x), "=f"(v.y) : "l"(p));
    return v;
}

// one k-step: combine W/D, broadcast-load PAIRS x-pairs from smem, accumulate
template <int PAIRS>
__device__ __forceinline__ void kstep(int k, float2 w2, float2 d2, unsigned xa,
                                      unsigned long long* acc)
{
    float wv0 = fmaf(d2.x, 0.1f, w2.x);
    float wv1 = fmaf(d2.y, 0.1f, w2.y);
    unsigned long long wva = dup2(wv0);
    unsigned long long wvb = dup2(wv1);

    unsigned a = xa + (unsigned)k * (CHUNK * 4);
    unsigned long long xp[PAIRS];
#pragma unroll
    for (int p = 0; p < PAIRS; p += 2) {
        asm volatile("ld.shared.v2.b64 {%0,%1},[%2];"
                     : "=l"(xp[p]), "=l"(xp[p + 1]) : "r"(a + (unsigned)(8 * p)));
    }
#pragma unroll
    for (int p = 0; p < PAIRS; ++p) {
        acc[p]         = fma2(xp[p], wva, acc[p]);
        acc[PAIRS + p] = fma2(xp[p], wvb, acc[PAIRS + p]);
    }
}

// full KHALF pass + cross-group reduce + store. All __syncthreads block-uniform.
template <int PAIRS>
__device__ __forceinline__ void compute_pass(
    const float2* __restrict__ wp, const float2* __restrict__ dp,
    unsigned xa, const short* __restrict__ s_list, int base, int mc,
    float2 bv, float* __restrict__ out, int c0, int kg, int t,
    float* __restrict__ red)
{
    unsigned long long acc[2 * PAIRS];
#pragma unroll
    for (int j = 0; j < 2 * PAIRS; ++j) acc[j] = 0ull;

    // prologue: fill pipeline (issue order pinned by volatile)
    float2 wbuf[PIPE], dbuf[PIPE];
#pragma unroll
    for (int p = 0; p < PIPE; ++p) {
        wbuf[p] = ldg2v(wp + (size_t)p * ROWF2);
        dbuf[p] = ldg2v(dp + (size_t)p * ROWF2);
    }

    // main: consume k=kk+p, prefetch k=kk+p+PIPE (always in-bounds, no clamp)
#pragma unroll 1
    for (int kk = 0; kk < KHALF - PIPE; kk += PIPE) {
#pragma unroll
        for (int p = 0; p < PIPE; ++p) {
            float2 w2 = wbuf[p], d2 = dbuf[p];
            wbuf[p] = ldg2v(wp + (size_t)(kk + PIPE + p) * ROWF2);
            dbuf[p] = ldg2v(dp + (size_t)(kk + PIPE + p) * ROWF2);
            kstep<PAIRS>(kk + p, w2, d2, xa, acc);
        }
    }
    // drain tail
#pragma unroll
    for (int p = 0; p < PIPE; ++p) {
        kstep<PAIRS>(KHALF - PIPE + p, wbuf[p], dbuf[p], xa, acc);
    }

    // ---- reduce group 1 -> group 0 via red (aliases xs; xs is dead now) ----
    __syncthreads();
    if (kg == 1) {
#pragma unroll
        for (int pr = 0; pr < PAIRS; ++pr) {
            float lo, hi;
            unpack2(acc[pr], lo, hi);
            red[(2 * pr + 0) * 128 + t] = lo;
            red[(2 * pr + 1) * 128 + t] = hi;
            unpack2(acc[PAIRS + pr], lo, hi);
            red[(2 * PAIRS + 2 * pr + 0) * 128 + t] = lo;
            red[(2 * PAIRS + 2 * pr + 1) * 128 + t] = hi;
        }
    }
    __syncthreads();
    if (kg == 0) {
        float v0[2 * PAIRS], v1[2 * PAIRS];
#pragma unroll
        for (int pr = 0; pr < PAIRS; ++pr) {
            float lo, hi;
            unpack2(acc[pr], lo, hi);
            v0[2 * pr + 0] = lo + red[(2 * pr + 0) * 128 + t];
            v0[2 * pr + 1] = hi + red[(2 * pr + 1) * 128 + t];
            unpack2(acc[PAIRS + pr], lo, hi);
            v1[2 * pr + 0] = lo + red[(2 * PAIRS + 2 * pr + 0) * 128 + t];
            v1[2 * pr + 1] = hi + red[(2 * PAIRS + 2 * pr + 1) * 128 + t];
        }
#pragma unroll
        for (int i = 0; i < 2 * PAIRS; ++i) {
            if (i < mc) {
                int n = s_list[base + i];
                float2 o = make_float2(v0[i] + bv.x, v1[i] + bv.y);
                *(float2*)(out + (size_t)n * OUT_F + c0) = o;
            }
        }
    }
}

__global__ void __launch_bounds__(THREADS, 2)
lms_kernel(const float* __restrict__ X,
           const int* __restrict__ hix,
           const int* __restrict__ six,
           const float* __restrict__ W,
           const float* __restrict__ D,
           const float* __restrict__ B,
           float* __restrict__ out)
{
    __shared__ int   s_cnt;
    __shared__ short s_list[N_SAMPLES];
    __shared__ __align__(16) float xs[IN_F * CHUNK];   // 32 KB; also reused as `red`

    const int tid = threadIdx.x;
    const int g   = blockIdx.y;            // combo
    const int h   = g >> 2;
    const int sp  = g & 3;
    const int kg  = tid >> 7;              // k-group 0/1
    const int t   = tid & 127;
    const int c0  = blockIdx.x * COLS_PER_BLOCK + t * 2;

    // ---- Phase A: build sample list for this combo ----
    if (tid == 0) s_cnt = 0;
    __syncthreads();
    for (int n = tid; n < N_SAMPLES; n += THREADS) {
        if (hix[n] == h && six[n] == sp) {
            int p = atomicAdd(&s_cnt, 1);
            s_list[p] = (short)n;
        }
    }
    __syncthreads();
    const int m = s_cnt;
    if (m == 0) return;                    // uniform across block

    const float2* wp = (const float2*)(W + (size_t)h * (IN_F * OUT_F)
                                         + (size_t)(kg * KHALF) * OUT_F + c0);
    const float2* dp = (const float2*)(D + (size_t)g * (IN_F * OUT_F)
                                         + (size_t)(kg * KHALF) * OUT_F + c0);
    const float2  bv = *(const float2*)(B + h * OUT_F + c0);
    const unsigned xs_addr = (unsigned)__cvta_generic_to_shared(xs);
    const unsigned xa = xs_addr + (unsigned)(kg * KHALF * (CHUNK * 4));

    // staging mapping: s = tid&15 (sample slot), q0 = tid>>4 (float4 base)
    const int s  = tid & 15;
    const int q0 = tid >> 4;               // 0..15

    // Nearly always a single pass (P[m>16] ~ 0.4% per combo).
    for (int base = 0; base < m; base += CHUNK) {
        // ---- stage x chunk transposed into smem (zero-padded) ----
        const int  sg    = base + s;
        const bool valid = sg < m;
        const float4* xrow =
            valid ? (const float4*)(X + (size_t)s_list[sg] * IN_F) : (const float4*)X;
#pragma unroll
        for (int i = 0; i < 8; ++i) {
            int Q = q0 + i * 16;           // 0..127
            float4 v = valid ? __ldg(xrow + Q) : make_float4(0.f, 0.f, 0.f, 0.f);
            int k0 = Q * 4;
            xs[(k0 + 0) * CHUNK + s] = v.x;
            xs[(k0 + 1) * CHUNK + s] = v.y;
            xs[(k0 + 2) * CHUNK + s] = v.z;
            xs[(k0 + 3) * CHUNK + s] = v.w;
        }
        __syncthreads();

        int mc = m - base;
        if (mc > CHUNK) mc = CHUNK;

        if (mc > 8) compute_pass<8>(wp, dp, xa, s_list, base, mc, bv, out, c0, kg, t, xs);
        else        compute_pass<4>(wp, dp, xa, s_list, base, mc, bv, out, c0, kg, t, xs);

        __syncthreads();                   // before next pass restages xs
    }
}

extern "C" void kernel_launch(void* const* d_in, const int* in_sizes, int n_in,
                              void* d_out, int out_size)
{
    const float* X   = (const float*)d_in[0];
    const int*   hix = (const int*)d_in[1];
    const int*   six = (const int*)d_in[2];
    const float* W   = (const float*)d_in[3];
    const float* D   = (const float*)d_in[4];
    const float* B   = (const float*)d_in[5];
    float*       out = (float*)d_out;

    dim3 grid(OUT_F / COLS_PER_BLOCK, N_COMBO);   // (2, 128) = 256 blocks
    lms_kernel<<<grid, THREADS>>>(X, hix, six, W, D, B, out);
}